// round 2
// baseline (speedup 1.0000x reference)
#include <cuda_runtime.h>

// AttentionGate fused kernel (fp32 SIMT baseline).
//
// out[b,c,hw] = sigmoid( Wpsi . LN( relu(Wx@x + Wg@g + bxg) ) + bpsi ) * x[b,c,hw]
//
// Per batch b: Y = Wx * X_b + Wg * G_b where X_b is [C=256, HW=4096] (channel
// planes contiguous in hw). One block = one batch x 64-pixel tile, computes all
// 256 output channels so the channel-LayerNorm + psi epilogue is block-local.

#define CC      256
#define HWSZ    4096
#define NPIX    64
#define KC      16
#define LN_EPS  1e-5f

__global__ __launch_bounds__(256, 2)
void attn_gate_fused(const float* __restrict__ x,
                     const float* __restrict__ g,
                     const float* __restrict__ Wx,
                     const float* __restrict__ Wg,
                     const float* __restrict__ Wpsi,
                     const float* __restrict__ ln_gamma,
                     const float* __restrict__ ln_beta,
                     const float* __restrict__ bxg,
                     const float* __restrict__ bpsi,
                     float* __restrict__ out)
{
    __shared__ float As[KC][CC];      // A tile, stored [k][o]  (16 KB)
    __shared__ float Bs[KC][NPIX];    // B tile, [k][pix]       (4 KB)
    __shared__ float sGamma[CC], sBeta[CC], sBxg[CC], sWpsi[CC];
    __shared__ float sBpsi;

    const int tid  = threadIdx.x;
    const int blk  = blockIdx.x;           // 0..1023
    const int b    = blk >> 6;             // 64 pixel-tiles per batch
    const int pix0 = (blk & 63) * NPIX;

    const int to = tid & 15;               // out-channel group (16 ch each)
    const int tp = tid >> 4;               // pixel group (4 pix each)

    // epilogue params to smem (256 threads, C==256)
    sGamma[tid] = ln_gamma[tid];
    sBeta[tid]  = ln_beta[tid];
    sBxg[tid]   = bxg[tid];
    sWpsi[tid]  = Wpsi[tid];
    if (tid == 0) sBpsi = bpsi[0];

    float acc[16][4];                      // [ii*4+iii][pix j]
    #pragma unroll
    for (int i = 0; i < 16; i++)
        #pragma unroll
        for (int j = 0; j < 4; j++) acc[i][j] = 0.f;

    const long xbase = (long)b * CC * HWSZ + pix0;

    // K = 512 (x-half then g-half), chunks of 16
    for (int kt = 0; kt < 32; ++kt) {
        const float* W = (kt < 16) ? Wx : Wg;
        const float* X = (kt < 16) ? x  : g;
        const int kloc = (kt & 15) * KC;   // 0..240 within that half

        // A tile: thread `tid` loads W[tid][kloc..kloc+15] -> As[k][tid]
        {
            const float4* src = (const float4*)(W + tid * CC + kloc);
            #pragma unroll
            for (int q = 0; q < 4; q++) {
                float4 v = src[q];
                As[q * 4 + 0][tid] = v.x;
                As[q * 4 + 1][tid] = v.y;
                As[q * 4 + 2][tid] = v.z;
                As[q * 4 + 3][tid] = v.w;
            }
        }
        // B tile: 16 rows x 64 pixels, 1 float4 per thread
        {
            const int kb = tid >> 4;
            const int p4 = (tid & 15) * 4;
            float4 v = *(const float4*)(X + xbase + (long)(kloc + kb) * HWSZ + p4);
            *(float4*)&Bs[kb][p4] = v;
        }
        __syncthreads();

        #pragma unroll
        for (int kk = 0; kk < KC; kk++) {
            float4 bv = *(const float4*)&Bs[kk][tp * 4];
            float bf0 = bv.x, bf1 = bv.y, bf2 = bv.z, bf3 = bv.w;
            #pragma unroll
            for (int ii = 0; ii < 4; ii++) {
                float4 av = *(const float4*)&As[kk][to * 4 + ii * 64];
                acc[ii*4+0][0] += av.x * bf0; acc[ii*4+0][1] += av.x * bf1;
                acc[ii*4+0][2] += av.x * bf2; acc[ii*4+0][3] += av.x * bf3;
                acc[ii*4+1][0] += av.y * bf0; acc[ii*4+1][1] += av.y * bf1;
                acc[ii*4+1][2] += av.y * bf2; acc[ii*4+1][3] += av.y * bf3;
                acc[ii*4+2][0] += av.z * bf0; acc[ii*4+2][1] += av.z * bf1;
                acc[ii*4+2][2] += av.z * bf2; acc[ii*4+2][3] += av.z * bf3;
                acc[ii*4+3][0] += av.w * bf0; acc[ii*4+3][1] += av.w * bf1;
                acc[ii*4+3][2] += av.w * bf2; acc[ii*4+3][3] += av.w * bf3;
            }
        }
        __syncthreads();
    }

    // ---- epilogue: relu(+bias), LayerNorm over channels, psi, sigmoid, gate ----
    // thread's channels: o = to*4 + ii*64 + iii ; pixels: p = pix0 + tp*4 + j
    float s1[4] = {0.f, 0.f, 0.f, 0.f};
    float s2[4] = {0.f, 0.f, 0.f, 0.f};
    #pragma unroll
    for (int ii = 0; ii < 4; ii++) {
        #pragma unroll
        for (int iii = 0; iii < 4; iii++) {
            const int o = to * 4 + ii * 64 + iii;
            const float bo = sBxg[o];
            #pragma unroll
            for (int j = 0; j < 4; j++) {
                float v = fmaxf(acc[ii*4+iii][j] + bo, 0.f);
                acc[ii*4+iii][j] = v;          // reuse acc as v storage
                s1[j] += v;
                s2[j] += v * v;
            }
        }
    }
    // reduce across the 16 threads (same tp) that hold one pixel's 256 channels.
    // those threads are 16 consecutive lanes, so xor-shuffles 1..8 stay inside.
    #pragma unroll
    for (int m = 1; m < 16; m <<= 1) {
        #pragma unroll
        for (int j = 0; j < 4; j++) {
            s1[j] += __shfl_xor_sync(0xffffffffu, s1[j], m);
            s2[j] += __shfl_xor_sync(0xffffffffu, s2[j], m);
        }
    }
    float meanv[4], rstd[4];
    #pragma unroll
    for (int j = 0; j < 4; j++) {
        meanv[j] = s1[j] * (1.0f / 256.0f);
        float var = s2[j] * (1.0f / 256.0f) - meanv[j] * meanv[j];
        rstd[j] = rsqrtf(var + LN_EPS);
    }

    float sp[4] = {0.f, 0.f, 0.f, 0.f};
    #pragma unroll
    for (int ii = 0; ii < 4; ii++) {
        #pragma unroll
        for (int iii = 0; iii < 4; iii++) {
            const int o  = to * 4 + ii * 64 + iii;
            const float ga = sGamma[o], be = sBeta[o], wp = sWpsi[o];
            #pragma unroll
            for (int j = 0; j < 4; j++) {
                float n = (acc[ii*4+iii][j] - meanv[j]) * rstd[j] * ga + be;
                sp[j] += n * wp;
            }
        }
    }
    #pragma unroll
    for (int m = 1; m < 16; m <<= 1) {
        #pragma unroll
        for (int j = 0; j < 4; j++)
            sp[j] += __shfl_xor_sync(0xffffffffu, sp[j], m);
    }
    float sig[4];
    #pragma unroll
    for (int j = 0; j < 4; j++) {
        float z = sp[j] + sBpsi;
        sig[j] = 1.0f / (1.0f + expf(-z));
    }

    // out[b, o, pix0 + tp*4 + j] = sig[j] * x[b, o, same]
    #pragma unroll
    for (int ii = 0; ii < 4; ii++) {
        #pragma unroll
        for (int iii = 0; iii < 4; iii++) {
            const int o = to * 4 + ii * 64 + iii;
            const long base = (long)b * CC * HWSZ + (long)o * HWSZ + pix0 + tp * 4;
            float4 xv = *(const float4*)(x + base);
            float4 ov;
            ov.x = sig[0] * xv.x;
            ov.y = sig[1] * xv.y;
            ov.z = sig[2] * xv.z;
            ov.w = sig[3] * xv.w;
            *(float4*)(out + base) = ov;
        }
    }
}

extern "C" void kernel_launch(void* const* d_in, const int* in_sizes, int n_in,
                              void* d_out, int out_size)
{
    // metadata order: x, g, Wx, Wg, Wpsi, ln_gamma, ln_beta, bxg, bpsi
    const float* x        = (const float*)d_in[0];
    const float* g        = (const float*)d_in[1];
    const float* Wx       = (const float*)d_in[2];
    const float* Wg       = (const float*)d_in[3];
    const float* Wpsi     = (const float*)d_in[4];
    const float* ln_gamma = (const float*)d_in[5];
    const float* ln_beta  = (const float*)d_in[6];
    const float* bxg      = (const float*)d_in[7];
    const float* bpsi     = (const float*)d_in[8];
    float* out = (float*)d_out;

    // 16 batches * (4096/64) pixel tiles = 1024 blocks
    attn_gate_fused<<<1024, 256>>>(x, g, Wx, Wg, Wpsi, ln_gamma, ln_beta,
                                   bxg, bpsi, out);
}

// round 5
// speedup vs baseline: 1.7767x; 1.7767x over previous
#include <cuda_runtime.h>
#include <cuda_bf16.h>
#include <cstdint>

#define CC     256
#define HWSZ   4096
#define KTOT   512       // x (256) then g (256)
#define PIXT   64        // pixels per CTA
#define KCH    32        // K per chunk
#define NCHUNK 16
#define LN_EPS 1e-5f

// ---- W split scratch (L2-resident, 256KB each) ----
__device__ __nv_bfloat16 g_W_hi[CC * KTOT];   // [o][k], k = ch (x) then 256+ch (g)
__device__ __nv_bfloat16 g_W_lo[CC * KTOT];

__device__ __forceinline__ uint32_t smem_u32(const void* p) {
    uint32_t a;
    asm("{ .reg .u64 t; cvta.to.shared.u64 t, %1; cvt.u32.u64 %0, t; }"
        : "=r"(a) : "l"(p));
    return a;
}

__device__ __forceinline__ void ldsm_x4(uint32_t* r, uint32_t a) {
    asm volatile("ldmatrix.sync.aligned.m8n8.x4.shared.b16 {%0,%1,%2,%3}, [%4];"
                 : "=r"(r[0]), "=r"(r[1]), "=r"(r[2]), "=r"(r[3]) : "r"(a));
}
__device__ __forceinline__ void ldsm_x4_t(uint32_t* r, uint32_t a) {
    asm volatile("ldmatrix.sync.aligned.m8n8.x4.trans.shared.b16 {%0,%1,%2,%3}, [%4];"
                 : "=r"(r[0]), "=r"(r[1]), "=r"(r[2]), "=r"(r[3]) : "r"(a));
}
__device__ __forceinline__ void mma_bf16(float* c, const uint32_t* a,
                                         uint32_t b0, uint32_t b1) {
    asm volatile(
        "mma.sync.aligned.m16n8k16.row.col.f32.bf16.bf16.f32 "
        "{%0,%1,%2,%3}, {%4,%5,%6,%7}, {%8,%9}, {%0,%1,%2,%3};"
        : "+f"(c[0]), "+f"(c[1]), "+f"(c[2]), "+f"(c[3])
        : "r"(a[0]), "r"(a[1]), "r"(a[2]), "r"(a[3]), "r"(b0), "r"(b1));
}

#define CP_ASYNC16(sa, ga) \
    asm volatile("cp.async.cg.shared.global [%0], [%1], 16;" \
                 :: "r"(sa), "l"(ga) : "memory")
#define CP_COMMIT() asm volatile("cp.async.commit_group;" ::: "memory")
#define CP_WAIT0()  asm volatile("cp.async.wait_group 0;" ::: "memory")

__device__ __forceinline__ uint32_t pack_hi(float x0, float x1) {
    __nv_bfloat162 h = __floats2bfloat162_rn(x0, x1);
    return *reinterpret_cast<uint32_t*>(&h);
}
__device__ __forceinline__ uint32_t pack_lo(float x0, float x1) {
    float r0 = x0 - __bfloat162float(__float2bfloat16(x0));
    float r1 = x1 - __bfloat162float(__float2bfloat16(x1));
    __nv_bfloat162 h = __floats2bfloat162_rn(r0, r1);
    return *reinterpret_cast<uint32_t*>(&h);
}

// ---- prep: split W into bf16 hi/lo, layout [o][k0..511] ----
__global__ void prep_w(const float* __restrict__ Wx, const float* __restrict__ Wg)
{
    int idx = blockIdx.x * blockDim.x + threadIdx.x;   // 0..131071
    int o = idx >> 9, k = idx & 511;
    float v = (k < 256) ? Wx[o * 256 + k] : Wg[o * 256 + (k - 256)];
    __nv_bfloat16 hi = __float2bfloat16(v);
    g_W_hi[idx] = hi;
    g_W_lo[idx] = __float2bfloat16(v - __bfloat162float(hi));
}

// ---------------- smem layout (dynamic) ----------------
#define OFF_U     0
#define OFF_BXG   1024
#define OFF_SIG   2048
#define OFF_SUMS  2304
#define OFF_RED   4352
#define OFF_TOT   4416
#define OFF_TILE  8192
#define A_STRIDE  144     // 64 pix * 2B + 16 pad
#define B_STRIDE  80      // 32 k * 2B + 16 pad
#define A_HI      0
#define A_LO      4608
#define B_HI      9216
#define B_LO      29696
#define BUF_SZ    50176
#define SMEM_TOTAL (OFF_TILE + 2 * BUF_SZ)   // 108544

__global__ void __launch_bounds__(256, 1)
attn_gate_hmma(const float* __restrict__ x,
               const float* __restrict__ g,
               const float* __restrict__ ln_gamma,
               const float* __restrict__ ln_beta,
               const float* __restrict__ bxg,
               const float* __restrict__ Wpsi,
               const float* __restrict__ bpsi,
               float* __restrict__ out)
{
    extern __shared__ char smem[];
    const uint32_t sb = smem_u32(smem);
    const int tid = threadIdx.x;
    const int wid = tid >> 5, lid = tid & 31;
    const int pixgrp = wid >> 1;          // 0..3 (16 pixels each)
    const int nhalf  = wid & 1;           // 0/1 (128 channels each)
    const int b    = blockIdx.x >> 6;
    const int pix0 = (blockIdx.x & 63) * PIXT;

    float* sU   = (float*)(smem + OFF_U);
    float* sBxg = (float*)(smem + OFF_BXG);
    float* sSig = (float*)(smem + OFF_SIG);
    float4* sSums = (float4*)(smem + OFF_SUMS);
    float2* sRed  = (float2*)(smem + OFF_RED);
    float2* sTot  = (float2*)(smem + OFF_TOT);

    // ---- B tile async copy: thread = one of 256 output-channel rows ----
    #define CPA_B(c, buf) do {                                                 \
        uint32_t bs = sb + OFF_TILE + (buf) * BUF_SZ;                          \
        const char* wh = (const char*)(g_W_hi + (size_t)tid * KTOT + (c) * KCH); \
        const char* wl = (const char*)(g_W_lo + (size_t)tid * KTOT + (c) * KCH); \
        uint32_t rh = bs + B_HI + tid * B_STRIDE;                              \
        uint32_t rl = bs + B_LO + tid * B_STRIDE;                              \
        CP_ASYNC16(rh,      wh);      CP_ASYNC16(rh + 16, wh + 16);            \
        CP_ASYNC16(rh + 32, wh + 32); CP_ASYNC16(rh + 48, wh + 48);            \
        CP_ASYNC16(rl,      wl);      CP_ASYNC16(rl + 16, wl + 16);            \
        CP_ASYNC16(rl + 32, wl + 32); CP_ASYNC16(rl + 48, wl + 48);            \
    } while (0)

    // ---- A tile: 32 k-rows x 64 px, fp32->bf16 hi/lo via registers ----
    float4 pa0, pa1;
    const int arow = tid >> 4;            // 0..15 (+16 for second row)
    const int apq  = tid & 15;            // pixel quad

    #define LDG_A(c) do {                                                      \
        const float* asrc = (((c) < 8) ? x : g) +                              \
            ((size_t)b * CC + ((c) & 7) * KCH) * HWSZ + pix0;                  \
        pa0 = *(const float4*)(asrc + (size_t)arow * HWSZ + apq * 4);          \
        pa1 = *(const float4*)(asrc + (size_t)(arow + 16) * HWSZ + apq * 4);   \
    } while (0)

    #define STS_A(buf) do {                                                    \
        char* base = smem + OFF_TILE + (buf) * BUF_SZ;                         \
        uint32_t h0 = pack_hi(pa0.x, pa0.y), h1 = pack_hi(pa0.z, pa0.w);       \
        uint32_t l0 = pack_lo(pa0.x, pa0.y), l1 = pack_lo(pa0.z, pa0.w);       \
        *(uint2*)(base + A_HI + arow * A_STRIDE + apq * 8) = make_uint2(h0, h1); \
        *(uint2*)(base + A_LO + arow * A_STRIDE + apq * 8) = make_uint2(l0, l1); \
        h0 = pack_hi(pa1.x, pa1.y); h1 = pack_hi(pa1.z, pa1.w);                \
        l0 = pack_lo(pa1.x, pa1.y); l1 = pack_lo(pa1.z, pa1.w);                \
        *(uint2*)(base + A_HI + (arow + 16) * A_STRIDE + apq * 8) = make_uint2(h0, h1); \
        *(uint2*)(base + A_LO + (arow + 16) * A_STRIDE + apq * 8) = make_uint2(l0, l1); \
    } while (0)

    {   // epilogue params + block totals su = sum(wpsi*gamma), sbb = sum(wpsi*beta)
        float wp = Wpsi[tid];
        float u  = wp * ln_gamma[tid];
        float wb = wp * ln_beta[tid];
        sU[tid]   = u;
        sBxg[tid] = bxg[tid];
        float us = u, ws = wb;
        #pragma unroll
        for (int m = 16; m >= 1; m >>= 1) {
            us += __shfl_xor_sync(0xffffffffu, us, m);
            ws += __shfl_xor_sync(0xffffffffu, ws, m);
        }
        if (lid == 0) sRed[wid] = make_float2(us, ws);
    }
    __syncthreads();
    if (tid == 0) {
        float us = 0.f, ws = 0.f;
        #pragma unroll
        for (int w = 0; w < 8; ++w) { us += sRed[w].x; ws += sRed[w].y; }
        sTot[0] = make_float2(us, ws);
    }

    float acc[16][4];
    #pragma unroll
    for (int j = 0; j < 16; ++j)
        #pragma unroll
        for (int q = 0; q < 4; ++q) acc[j][q] = 0.f;

    // prologue: chunk 0 into buffer 0
    CPA_B(0, 0);
    CP_COMMIT();
    LDG_A(0);
    STS_A(0);
    CP_WAIT0();
    __syncthreads();

    const int m0 = pixgrp * 16;
    const int al_k = (lid & 7) + ((lid >> 4) << 3);
    const int al_m = m0 + (((lid >> 3) & 1) << 3);
    const int bl_n = ((lid >> 4) << 3) + (lid & 7);
    const int bl_k = ((lid >> 3) & 1) << 3;

    for (int c = 0; c < NCHUNK; ++c) {
        if (c < NCHUNK - 1) {
            CPA_B(c + 1, (c + 1) & 1);
            CP_COMMIT();
            LDG_A(c + 1);
        }

        const uint32_t tb = sb + OFF_TILE + (c & 1) * BUF_SZ;
        #pragma unroll
        for (int ks = 0; ks < 2; ++ks) {
            const int k0 = ks * 16;
            uint32_t a_addr = tb + A_HI + (k0 + al_k) * A_STRIDE + al_m * 2;
            uint32_t ah[4], al[4];
            ldsm_x4_t(ah, a_addr);
            ldsm_x4_t(al, a_addr + (A_LO - A_HI));
            #pragma unroll
            for (int ntt = 0; ntt < 8; ++ntt) {
                const int nb = nhalf * 128 + ntt * 16;
                uint32_t b_addr = tb + B_HI + (nb + bl_n) * B_STRIDE + (k0 + bl_k) * 2;
                uint32_t bh[4], bl[4];
                ldsm_x4(bh, b_addr);
                ldsm_x4(bl, b_addr + (B_LO - B_HI));
                const int j = ntt * 2;
                mma_bf16(acc[j],     ah, bh[0], bh[1]);
                mma_bf16(acc[j],     al, bh[0], bh[1]);
                mma_bf16(acc[j],     ah, bl[0], bl[1]);
                mma_bf16(acc[j + 1], ah, bh[2], bh[3]);
                mma_bf16(acc[j + 1], al, bh[2], bh[3]);
                mma_bf16(acc[j + 1], ah, bl[2], bl[3]);
            }
        }
        if (c < NCHUNK - 1) {
            STS_A((c + 1) & 1);
            CP_WAIT0();
        }
        __syncthreads();
    }

    // ---- epilogue: relu(+bias), LN over 256 ch, psi, sigmoid ----
    {
        float s1a = 0.f, s2a = 0.f, sya = 0.f;
        float s1b = 0.f, s2b = 0.f, syb = 0.f;
        #pragma unroll
        for (int j = 0; j < 16; ++j) {
            const int c0 = nhalf * 128 + j * 8 + 2 * (lid & 3);
            const float bx0 = sBxg[c0], bx1 = sBxg[c0 + 1];
            const float u0 = sU[c0], u1 = sU[c0 + 1];
            float y;
            y = fmaxf(acc[j][0] + bx0, 0.f); s1a += y; s2a += y * y; sya += u0 * y;
            y = fmaxf(acc[j][1] + bx1, 0.f); s1a += y; s2a += y * y; sya += u1 * y;
            y = fmaxf(acc[j][2] + bx0, 0.f); s1b += y; s2b += y * y; syb += u0 * y;
            y = fmaxf(acc[j][3] + bx1, 0.f); s1b += y; s2b += y * y; syb += u1 * y;
        }
        #pragma unroll
        for (int m = 1; m <= 2; m <<= 1) {
            s1a += __shfl_xor_sync(0xffffffffu, s1a, m);
            s2a += __shfl_xor_sync(0xffffffffu, s2a, m);
            sya += __shfl_xor_sync(0xffffffffu, sya, m);
            s1b += __shfl_xor_sync(0xffffffffu, s1b, m);
            s2b += __shfl_xor_sync(0xffffffffu, s2b, m);
            syb += __shfl_xor_sync(0xffffffffu, syb, m);
        }
        if ((lid & 3) == 0) {
            const int p = pixgrp * 16 + (lid >> 2);
            sSums[p * 2 + nhalf]       = make_float4(s1a, s2a, sya, 0.f);
            sSums[(p + 8) * 2 + nhalf] = make_float4(s1b, s2b, syb, 0.f);
        }
    }
    __syncthreads();
    if (tid < PIXT) {
        float4 h0 = sSums[tid * 2], h1 = sSums[tid * 2 + 1];
        float s1 = h0.x + h1.x, s2 = h0.y + h1.y, sy = h0.z + h1.z;
        float2 tot = sTot[0];
        float mean = s1 * (1.f / 256.f);
        float var  = s2 * (1.f / 256.f) - mean * mean;
        float rstd = rsqrtf(var + LN_EPS);
        float z = rstd * (sy - mean * tot.x) + tot.y + bpsi[0];
        sSig[tid] = 1.f / (1.f + expf(-z));
    }
    __syncthreads();

    // ---- gate: out[b,o,pix] = sig[pix] * x[b,o,pix] ----
    const size_t xbase = (size_t)b * CC * HWSZ + pix0;
    const int pq = tid & 15;
    float4 sg = *(const float4*)(sSig + pq * 4);
    #pragma unroll
    for (int it = 0; it < 16; ++it) {
        const int o = (tid >> 4) + it * 16;
        const size_t off = xbase + (size_t)o * HWSZ + pq * 4;
        float4 xv = *(const float4*)(x + off);
        float4 ov;
        ov.x = sg.x * xv.x; ov.y = sg.y * xv.y;
        ov.z = sg.z * xv.z; ov.w = sg.w * xv.w;
        *(float4*)(out + off) = ov;
    }
}

extern "C" void kernel_launch(void* const* d_in, const int* in_sizes, int n_in,
                              void* d_out, int out_size)
{
    const float* x        = (const float*)d_in[0];
    const float* g        = (const float*)d_in[1];
    const float* Wx       = (const float*)d_in[2];
    const float* Wg       = (const float*)d_in[3];
    const float* Wpsi     = (const float*)d_in[4];
    const float* ln_gamma = (const float*)d_in[5];
    const float* ln_beta  = (const float*)d_in[6];
    const float* bxg      = (const float*)d_in[7];
    const float* bpsi     = (const float*)d_in[8];
    float* out = (float*)d_out;

    cudaFuncSetAttribute(attn_gate_hmma,
                         cudaFuncAttributeMaxDynamicSharedMemorySize, SMEM_TOTAL);

    prep_w<<<512, 256>>>(Wx, Wg);
    attn_gate_hmma<<<1024, 256, SMEM_TOTAL>>>(x, g, ln_gamma, ln_beta, bxg,
                                              Wpsi, bpsi, out);
}

// round 7
// speedup vs baseline: 1.8964x; 1.0674x over previous
#include <cuda_runtime.h>
#include <cuda_bf16.h>
#include <cstdint>

#define CC     256
#define HWSZ   4096
#define KTOT   512       // x (256) then g (256)
#define PIXT   64        // pixels per CTA
#define KCH    32        // K per chunk
#define NCHUNK 16
#define NTHR   512
#define LN_EPS 1e-5f

// ---- W split scratch (L2-resident, 256KB each) ----
__device__ __nv_bfloat16 g_W_hi[CC * KTOT];   // [o][k], k = ch (x) then 256+ch (g)
__device__ __nv_bfloat16 g_W_lo[CC * KTOT];

__device__ __forceinline__ uint32_t smem_u32(const void* p) {
    uint32_t a;
    asm("{ .reg .u64 t; cvta.to.shared.u64 t, %1; cvt.u32.u64 %0, t; }"
        : "=r"(a) : "l"(p));
    return a;
}

__device__ __forceinline__ void ldsm_x4(uint32_t* r, uint32_t a) {
    asm volatile("ldmatrix.sync.aligned.m8n8.x4.shared.b16 {%0,%1,%2,%3}, [%4];"
                 : "=r"(r[0]), "=r"(r[1]), "=r"(r[2]), "=r"(r[3]) : "r"(a));
}
__device__ __forceinline__ void ldsm_x4_t(uint32_t* r, uint32_t a) {
    asm volatile("ldmatrix.sync.aligned.m8n8.x4.trans.shared.b16 {%0,%1,%2,%3}, [%4];"
                 : "=r"(r[0]), "=r"(r[1]), "=r"(r[2]), "=r"(r[3]) : "r"(a));
}
__device__ __forceinline__ void mma_bf16(float* c, const uint32_t* a,
                                         uint32_t b0, uint32_t b1) {
    asm volatile(
        "mma.sync.aligned.m16n8k16.row.col.f32.bf16.bf16.f32 "
        "{%0,%1,%2,%3}, {%4,%5,%6,%7}, {%8,%9}, {%0,%1,%2,%3};"
        : "+f"(c[0]), "+f"(c[1]), "+f"(c[2]), "+f"(c[3])
        : "r"(a[0]), "r"(a[1]), "r"(a[2]), "r"(a[3]), "r"(b0), "r"(b1));
}

#define CP_ASYNC16(sa, ga) \
    asm volatile("cp.async.cg.shared.global [%0], [%1], 16;" \
                 :: "r"(sa), "l"(ga) : "memory")
#define CP_COMMIT() asm volatile("cp.async.commit_group;" ::: "memory")
#define CP_WAIT0()  asm volatile("cp.async.wait_group 0;" ::: "memory")

__device__ __forceinline__ uint32_t pack_hi(float x0, float x1) {
    __nv_bfloat162 h = __floats2bfloat162_rn(x0, x1);
    return *reinterpret_cast<uint32_t*>(&h);
}
__device__ __forceinline__ uint32_t pack_lo(float x0, float x1) {
    float r0 = x0 - __bfloat162float(__float2bfloat16(x0));
    float r1 = x1 - __bfloat162float(__float2bfloat16(x1));
    __nv_bfloat162 h = __floats2bfloat162_rn(r0, r1);
    return *reinterpret_cast<uint32_t*>(&h);
}

// ---- prep: split W into bf16 hi/lo, layout [o][k0..511] ----
__global__ void prep_w(const float* __restrict__ Wx, const float* __restrict__ Wg)
{
    int idx = blockIdx.x * blockDim.x + threadIdx.x;   // 0..131071
    int o = idx >> 9, k = idx & 511;
    float v = (k < 256) ? Wx[o * 256 + k] : Wg[o * 256 + (k - 256)];
    __nv_bfloat16 hi = __float2bfloat16(v);
    g_W_hi[idx] = hi;
    g_W_lo[idx] = __float2bfloat16(v - __bfloat162float(hi));
}

// ---------------- smem layout (dynamic) ----------------
#define OFF_U     0
#define OFF_BXG   1024
#define OFF_SIG   2048
#define OFF_SUMS  2304     // 64 px * 4 quarters * float4 = 4096 B
#define OFF_RED   6400     // 16 * float2
#define OFF_TOT   6528
#define OFF_TILE  8192
#define A_STRIDE  144      // 64 pix * 2B + 16 pad
#define B_STRIDE  80       // 32 k * 2B + 16 pad
#define A_HI      0
#define A_LO      4608
#define B_HI      9216
#define B_LO      29696
#define BUF_SZ    50176
#define SMEM_TOTAL (OFF_TILE + 2 * BUF_SZ)   // 108544

__global__ void __launch_bounds__(NTHR, 1)
attn_gate_hmma(const float* __restrict__ x,
               const float* __restrict__ g,
               const float* __restrict__ ln_gamma,
               const float* __restrict__ ln_beta,
               const float* __restrict__ bxg,
               const float* __restrict__ Wpsi,
               const float* __restrict__ bpsi,
               float* __restrict__ out)
{
    extern __shared__ char smem[];
    const uint32_t sb = smem_u32(smem);
    const int tid = threadIdx.x;
    const int wid = tid >> 5, lid = tid & 31;
    const int pixgrp = wid >> 2;          // 0..3 (16 pixels each)
    const int nq     = wid & 3;           // 0..3 (64 channels each)
    const int b    = blockIdx.x >> 6;
    const int pix0 = (blockIdx.x & 63) * PIXT;

    float* sU   = (float*)(smem + OFF_U);
    float* sBxg = (float*)(smem + OFF_BXG);
    float* sSig = (float*)(smem + OFF_SIG);
    float4* sSums = (float4*)(smem + OFF_SUMS);
    float2* sRed  = (float2*)(smem + OFF_RED);
    float2* sTot  = (float2*)(smem + OFF_TOT);

    // ---- B tile async copy: 512 threads = 256 hi rows + 256 lo rows ----
    const int brow = tid & 255;
    const int bhl  = tid >> 8;            // 0 = hi, 1 = lo
    const __nv_bfloat16* bsrc_base = bhl ? g_W_lo : g_W_hi;
    const uint32_t bdst_off = (bhl ? B_LO : B_HI) + brow * B_STRIDE;

    #define CPA_B(c, buf) do {                                                 \
        uint32_t dst = sb + OFF_TILE + (buf) * BUF_SZ + bdst_off;              \
        const char* w = (const char*)(bsrc_base + (size_t)brow * KTOT + (c) * KCH); \
        CP_ASYNC16(dst,      w);      CP_ASYNC16(dst + 16, w + 16);            \
        CP_ASYNC16(dst + 32, w + 32); CP_ASYNC16(dst + 48, w + 48);            \
    } while (0)

    // ---- A tile: 32 k-rows x 64 px, one float4 per thread ----
    float4 pa0;
    const int arow = tid >> 4;            // 0..31
    const int apq  = tid & 15;            // pixel quad

    #define LDG_A(c) do {                                                      \
        const float* asrc = (((c) < 8) ? x : g) +                              \
            ((size_t)b * CC + ((c) & 7) * KCH) * HWSZ + pix0;                  \
        pa0 = *(const float4*)(asrc + (size_t)arow * HWSZ + apq * 4);          \
    } while (0)

    #define STS_A(buf) do {                                                    \
        char* base = smem + OFF_TILE + (buf) * BUF_SZ;                         \
        uint32_t h0 = pack_hi(pa0.x, pa0.y), h1 = pack_hi(pa0.z, pa0.w);       \
        uint32_t l0 = pack_lo(pa0.x, pa0.y), l1 = pack_lo(pa0.z, pa0.w);       \
        *(uint2*)(base + A_HI + arow * A_STRIDE + apq * 8) = make_uint2(h0, h1); \
        *(uint2*)(base + A_LO + arow * A_STRIDE + apq * 8) = make_uint2(l0, l1); \
    } while (0)

    if (tid < 256) {   // epilogue params + totals (su = Σwpsi*gamma, ws = Σwpsi*beta)
        float wp = Wpsi[tid];
        float u  = wp * ln_gamma[tid];
        float wb = wp * ln_beta[tid];
        sU[tid]   = u;
        sBxg[tid] = bxg[tid];
        float us = u, ws = wb;
        #pragma unroll
        for (int m = 16; m >= 1; m >>= 1) {
            us += __shfl_xor_sync(0xffffffffu, us, m);
            ws += __shfl_xor_sync(0xffffffffu, ws, m);
        }
        if (lid == 0) sRed[wid] = make_float2(us, ws);
    }
    __syncthreads();
    if (tid == 0) {
        float us = 0.f, ws = 0.f;
        #pragma unroll
        for (int w = 0; w < 8; ++w) { us += sRed[w].x; ws += sRed[w].y; }
        sTot[0] = make_float2(us, ws);
    }

    float acc[8][4];
    #pragma unroll
    for (int j = 0; j < 8; ++j)
        #pragma unroll
        for (int q = 0; q < 4; ++q) acc[j][q] = 0.f;

    // prologue: chunk 0 into buffer 0
    CPA_B(0, 0);
    CP_COMMIT();
    LDG_A(0);
    STS_A(0);
    CP_WAIT0();
    __syncthreads();

    const int m0 = pixgrp * 16;
    const int al_k = (lid & 7) + ((lid >> 4) << 3);
    const int al_m = m0 + (((lid >> 3) & 1) << 3);
    const int bl_n = ((lid >> 4) << 3) + (lid & 7);
    const int bl_k = ((lid >> 3) & 1) << 3;

    for (int c = 0; c < NCHUNK; ++c) {
        if (c < NCHUNK - 1) {
            CPA_B(c + 1, (c + 1) & 1);
            CP_COMMIT();
            LDG_A(c + 1);
        }

        const uint32_t tb = sb + OFF_TILE + (c & 1) * BUF_SZ;
        #pragma unroll
        for (int ks = 0; ks < 2; ++ks) {
            const int k0 = ks * 16;
            uint32_t a_addr = tb + A_HI + (k0 + al_k) * A_STRIDE + al_m * 2;
            uint32_t ah[4], al[4];
            ldsm_x4_t(ah, a_addr);
            ldsm_x4_t(al, a_addr + (A_LO - A_HI));
            #pragma unroll
            for (int ntt = 0; ntt < 4; ++ntt) {
                const int nb = nq * 64 + ntt * 16;
                uint32_t b_addr = tb + B_HI + (nb + bl_n) * B_STRIDE + (k0 + bl_k) * 2;
                uint32_t bh[4], bl[4];
                ldsm_x4(bh, b_addr);
                ldsm_x4(bl, b_addr + (B_LO - B_HI));
                const int j = ntt * 2;
                mma_bf16(acc[j],     ah, bh[0], bh[1]);
                mma_bf16(acc[j],     al, bh[0], bh[1]);
                mma_bf16(acc[j],     ah, bl[0], bl[1]);
                mma_bf16(acc[j + 1], ah, bh[2], bh[3]);
                mma_bf16(acc[j + 1], al, bh[2], bh[3]);
                mma_bf16(acc[j + 1], ah, bl[2], bl[3]);
            }
        }
        if (c < NCHUNK - 1) {
            STS_A((c + 1) & 1);
            CP_WAIT0();
        }
        __syncthreads();
    }

    // ---- epilogue: relu(+bias), LN over 256 ch, psi, sigmoid ----
    // thread rows: pixgrp*16 + (lid>>2) and +8 ; cols nq*64 + j*8 + 2*(lid&3)+{0,1}
    {
        float s1a = 0.f, s2a = 0.f, sya = 0.f;
        float s1b = 0.f, s2b = 0.f, syb = 0.f;
        #pragma unroll
        for (int j = 0; j < 8; ++j) {
            const int c0 = nq * 64 + j * 8 + 2 * (lid & 3);
            const float bx0 = sBxg[c0], bx1 = sBxg[c0 + 1];
            const float u0 = sU[c0], u1 = sU[c0 + 1];
            float y;
            y = fmaxf(acc[j][0] + bx0, 0.f); s1a += y; s2a += y * y; sya += u0 * y;
            y = fmaxf(acc[j][1] + bx1, 0.f); s1a += y; s2a += y * y; sya += u1 * y;
            y = fmaxf(acc[j][2] + bx0, 0.f); s1b += y; s2b += y * y; syb += u0 * y;
            y = fmaxf(acc[j][3] + bx1, 0.f); s1b += y; s2b += y * y; syb += u1 * y;
        }
        #pragma unroll
        for (int m = 1; m <= 2; m <<= 1) {
            s1a += __shfl_xor_sync(0xffffffffu, s1a, m);
            s2a += __shfl_xor_sync(0xffffffffu, s2a, m);
            sya += __shfl_xor_sync(0xffffffffu, sya, m);
            s1b += __shfl_xor_sync(0xffffffffu, s1b, m);
            s2b += __shfl_xor_sync(0xffffffffu, s2b, m);
            syb += __shfl_xor_sync(0xffffffffu, syb, m);
        }
        if ((lid & 3) == 0) {
            const int p = pixgrp * 16 + (lid >> 2);
            sSums[p * 4 + nq]       = make_float4(s1a, s2a, sya, 0.f);
            sSums[(p + 8) * 4 + nq] = make_float4(s1b, s2b, syb, 0.f);
        }
    }
    __syncthreads();
    if (tid < PIXT) {
        float4 h0 = sSums[tid * 4], h1 = sSums[tid * 4 + 1];
        float4 h2 = sSums[tid * 4 + 2], h3 = sSums[tid * 4 + 3];
        float s1 = h0.x + h1.x + h2.x + h3.x;
        float s2 = h0.y + h1.y + h2.y + h3.y;
        float sy = h0.z + h1.z + h2.z + h3.z;
        float2 tot = sTot[0];
        float mean = s1 * (1.f / 256.f);
        float var  = s2 * (1.f / 256.f) - mean * mean;
        float rstd = rsqrtf(var + LN_EPS);
        float z = rstd * (sy - mean * tot.x) + tot.y + bpsi[0];
        sSig[tid] = 1.f / (1.f + expf(-z));
    }
    __syncthreads();

    // ---- gate: out[b,o,pix] = sig[pix] * x[b,o,pix] ----
    const size_t xbase = (size_t)b * CC * HWSZ + pix0;
    const int pq = tid & 15;
    float4 sg = *(const float4*)(sSig + pq * 4);
    #pragma unroll
    for (int it = 0; it < 8; ++it) {
        const int o = (tid >> 4) + it * 32;
        const size_t off = xbase + (size_t)o * HWSZ + pq * 4;
        float4 xv = *(const float4*)(x + off);
        float4 ov;
        ov.x = sg.x * xv.x; ov.y = sg.y * xv.y;
        ov.z = sg.z * xv.z; ov.w = sg.w * xv.w;
        *(float4*)(out + off) = ov;
    }
}

extern "C" void kernel_launch(void* const* d_in, const int* in_sizes, int n_in,
                              void* d_out, int out_size)
{
    const float* x        = (const float*)d_in[0];
    const float* g        = (const float*)d_in[1];
    const float* Wx       = (const float*)d_in[2];
    const float* Wg       = (const float*)d_in[3];
    const float* Wpsi     = (const float*)d_in[4];
    const float* ln_gamma = (const float*)d_in[5];
    const float* ln_beta  = (const float*)d_in[6];
    const float* bxg      = (const float*)d_in[7];
    const float* bpsi     = (const float*)d_in[8];
    float* out = (float*)d_out;

    cudaFuncSetAttribute(attn_gate_hmma,
                         cudaFuncAttributeMaxDynamicSharedMemorySize, SMEM_TOTAL);

    prep_w<<<512, 256>>>(Wx, Wg);
    attn_gate_hmma<<<1024, NTHR, SMEM_TOTAL>>>(x, g, ln_gamma, ln_beta, bxg,
                                               Wpsi, bpsi, out);
}

// round 10
// speedup vs baseline: 1.8997x; 1.0017x over previous
#include <cuda_runtime.h>
#include <cuda_bf16.h>
#include <cstdint>

#define CC     256
#define HWSZ   4096
#define KTOT   512       // x (256) then g (256)
#define PIXT   64        // pixels per CTA
#define KCH    32        // K per chunk
#define NCHUNK 16
#define NTHR   512
#define LN_EPS 1e-5f

// ---- W split scratch (L2-resident, 256KB each) ----
__device__ __nv_bfloat16 g_W_hi[CC * KTOT];   // [o][k], k = ch (x) then 256+ch (g)
__device__ __nv_bfloat16 g_W_lo[CC * KTOT];

__device__ __forceinline__ uint32_t smem_u32(const void* p) {
    uint32_t a;
    asm("{ .reg .u64 t; cvta.to.shared.u64 t, %1; cvt.u32.u64 %0, t; }"
        : "=r"(a) : "l"(p));
    return a;
}

__device__ __forceinline__ void ldsm_x4(uint32_t* r, uint32_t a) {
    asm volatile("ldmatrix.sync.aligned.m8n8.x4.shared.b16 {%0,%1,%2,%3}, [%4];"
                 : "=r"(r[0]), "=r"(r[1]), "=r"(r[2]), "=r"(r[3]) : "r"(a));
}
__device__ __forceinline__ void ldsm_x4_t(uint32_t* r, uint32_t a) {
    asm volatile("ldmatrix.sync.aligned.m8n8.x4.trans.shared.b16 {%0,%1,%2,%3}, [%4];"
                 : "=r"(r[0]), "=r"(r[1]), "=r"(r[2]), "=r"(r[3]) : "r"(a));
}
__device__ __forceinline__ void mma_bf16(float* c, const uint32_t* a,
                                         uint32_t b0, uint32_t b1) {
    asm volatile(
        "mma.sync.aligned.m16n8k16.row.col.f32.bf16.bf16.f32 "
        "{%0,%1,%2,%3}, {%4,%5,%6,%7}, {%8,%9}, {%0,%1,%2,%3};"
        : "+f"(c[0]), "+f"(c[1]), "+f"(c[2]), "+f"(c[3])
        : "r"(a[0]), "r"(a[1]), "r"(a[2]), "r"(a[3]), "r"(b0), "r"(b1));
}

#define CP_ASYNC16(sa, ga) \
    asm volatile("cp.async.cg.shared.global [%0], [%1], 16;" \
                 :: "r"(sa), "l"(ga) : "memory")
#define CP_COMMIT() asm volatile("cp.async.commit_group;" ::: "memory")
#define CP_WAIT0()  asm volatile("cp.async.wait_group 0;" ::: "memory")

__device__ __forceinline__ uint32_t pack_hi(float x0, float x1) {
    __nv_bfloat162 h = __floats2bfloat162_rn(x0, x1);
    return *reinterpret_cast<uint32_t*>(&h);
}
__device__ __forceinline__ uint32_t pack_lo(float x0, float x1) {
    float r0 = x0 - __bfloat162float(__float2bfloat16(x0));
    float r1 = x1 - __bfloat162float(__float2bfloat16(x1));
    __nv_bfloat162 h = __floats2bfloat162_rn(r0, r1);
    return *reinterpret_cast<uint32_t*>(&h);
}

// ---- prep: split W into bf16 hi/lo, layout [o][k0..511] ----
__global__ void prep_w(const float* __restrict__ Wx, const float* __restrict__ Wg)
{
    int idx = blockIdx.x * blockDim.x + threadIdx.x;   // 0..131071
    int o = idx >> 9, k = idx & 511;
    float v = (k < 256) ? Wx[o * 256 + k] : Wg[o * 256 + (k - 256)];
    __nv_bfloat16 hi = __float2bfloat16(v);
    g_W_hi[idx] = hi;
    g_W_lo[idx] = __float2bfloat16(v - __bfloat162float(hi));
}

// ---------------- smem layout (dynamic) ----------------
#define OFF_U     0
#define OFF_BXG   1024
#define OFF_SIG   2048
#define OFF_SUMS  2304     // 64 px * 4 quarters * float4 = 4096 B
#define OFF_RED   6400     // 16 * float2
#define OFF_TOT   6528
#define OFF_TILE  8192
#define A_STRIDE  144      // 64 pix * 2B + 16 pad
#define B_STRIDE  80       // 32 k * 2B + 16 pad
#define A_HI      0
#define A_LO      4608
#define B_HI      9216
#define B_LO      29696
#define BUF_SZ    50176
#define SMEM_TOTAL (OFF_TILE + 2 * BUF_SZ)   // 108544

__global__ void __launch_bounds__(NTHR, 1)
attn_gate_hmma(const float* __restrict__ x,
               const float* __restrict__ g,
               const float* __restrict__ ln_gamma,
               const float* __restrict__ ln_beta,
               const float* __restrict__ bxg,
               const float* __restrict__ Wpsi,
               const float* __restrict__ bpsi,
               float* __restrict__ out)
{
    extern __shared__ char smem[];
    const uint32_t sb = smem_u32(smem);
    const int tid = threadIdx.x;
    const int wid = tid >> 5, lid = tid & 31;
    const int pixgrp = wid >> 2;          // 0..3 (16 pixels each)
    const int nq     = wid & 3;           // 0..3 (64 channels each)
    const int b    = blockIdx.x >> 6;
    const int pix0 = (blockIdx.x & 63) * PIXT;

    float* sU   = (float*)(smem + OFF_U);
    float* sBxg = (float*)(smem + OFF_BXG);
    float* sSig = (float*)(smem + OFF_SIG);
    float4* sSums = (float4*)(smem + OFF_SUMS);
    float2* sRed  = (float2*)(smem + OFF_RED);
    float2* sTot  = (float2*)(smem + OFF_TOT);

    // ---- B tile async copy: 512 threads = 256 hi rows + 256 lo rows ----
    const int brow = tid & 255;
    const int bhl  = tid >> 8;            // 0 = hi, 1 = lo
    const __nv_bfloat16* bsrc_base = bhl ? g_W_lo : g_W_hi;
    const uint32_t bdst_off = (bhl ? B_LO : B_HI) + brow * B_STRIDE;

    #define CPA_B(c, buf) do {                                                 \
        uint32_t dst = sb + OFF_TILE + (buf) * BUF_SZ + bdst_off;              \
        const char* w = (const char*)(bsrc_base + (size_t)brow * KTOT + (c) * KCH); \
        CP_ASYNC16(dst,      w);      CP_ASYNC16(dst + 16, w + 16);            \
        CP_ASYNC16(dst + 32, w + 32); CP_ASYNC16(dst + 48, w + 48);            \
    } while (0)

    // ---- A tile: 32 k-rows x 64 px, one float4 per thread ----
    float4 pa0;
    const int arow = tid >> 4;            // 0..31
    const int apq  = tid & 15;            // pixel quad

    #define LDG_A(c) do {                                                      \
        const float* asrc = (((c) < 8) ? x : g) +                              \
            ((size_t)b * CC + ((c) & 7) * KCH) * HWSZ + pix0;                  \
        pa0 = *(const float4*)(asrc + (size_t)arow * HWSZ + apq * 4);          \
    } while (0)

    #define STS_A(buf) do {                                                    \
        char* base = smem + OFF_TILE + (buf) * BUF_SZ;                         \
        uint32_t h0 = pack_hi(pa0.x, pa0.y), h1 = pack_hi(pa0.z, pa0.w);       \
        uint32_t l0 = pack_lo(pa0.x, pa0.y), l1 = pack_lo(pa0.z, pa0.w);       \
        *(uint2*)(base + A_HI + arow * A_STRIDE + apq * 8) = make_uint2(h0, h1); \
        *(uint2*)(base + A_LO + arow * A_STRIDE + apq * 8) = make_uint2(l0, l1); \
    } while (0)

    if (tid < 256) {   // epilogue params + totals (su = Σwpsi*gamma, ws = Σwpsi*beta)
        float wp = Wpsi[tid];
        float u  = wp * ln_gamma[tid];
        float wb = wp * ln_beta[tid];
        sU[tid]   = u;
        sBxg[tid] = bxg[tid];
        float us = u, ws = wb;
        #pragma unroll
        for (int m = 16; m >= 1; m >>= 1) {
            us += __shfl_xor_sync(0xffffffffu, us, m);
            ws += __shfl_xor_sync(0xffffffffu, ws, m);
        }
        if (lid == 0) sRed[wid] = make_float2(us, ws);
    }
    __syncthreads();
    if (tid == 0) {
        float us = 0.f, ws = 0.f;
        #pragma unroll
        for (int w = 0; w < 8; ++w) { us += sRed[w].x; ws += sRed[w].y; }
        sTot[0] = make_float2(us, ws);
    }

    float acc[8][4];
    #pragma unroll
    for (int j = 0; j < 8; ++j)
        #pragma unroll
        for (int q = 0; q < 4; ++q) acc[j][q] = 0.f;

    // prologue: chunk 0 into buffer 0
    CPA_B(0, 0);
    CP_COMMIT();
    LDG_A(0);
    STS_A(0);
    CP_WAIT0();
    __syncthreads();

    const int m0 = pixgrp * 16;
    const int al_k = (lid & 7) + ((lid >> 4) << 3);
    const int al_m = m0 + (((lid >> 3) & 1) << 3);
    const int bl_n = ((lid >> 4) << 3) + (lid & 7);
    const int bl_k = ((lid >> 3) & 1) << 3;

    for (int c = 0; c < NCHUNK; ++c) {
        if (c < NCHUNK - 1) {
            CPA_B(c + 1, (c + 1) & 1);
            CP_COMMIT();
            LDG_A(c + 1);
        }

        const uint32_t tb = sb + OFF_TILE + (c & 1) * BUF_SZ;

        // ---- software-pipelined MMA section ----
        // A fragments for both k-steps, loaded once per chunk
        uint32_t ah[2][4], al[2][4];
        // B fragment double buffer
        uint32_t bh[2][4], bl[2][4];

        const uint32_t a_addr0 = tb + A_HI + al_k * A_STRIDE + al_m * 2;
        const uint32_t a_addr1 = a_addr0 + 16 * A_STRIDE;
        const uint32_t b_base  = tb + B_HI + (nq * 64 + bl_n) * B_STRIDE + bl_k * 2;

        ldsm_x4_t(ah[0], a_addr0);
        ldsm_x4_t(al[0], a_addr0 + (A_LO - A_HI));
        ldsm_x4(bh[0], b_base);
        ldsm_x4(bl[0], b_base + (B_LO - B_HI));
        ldsm_x4_t(ah[1], a_addr1);
        ldsm_x4_t(al[1], a_addr1 + (A_LO - A_HI));

        #pragma unroll
        for (int s = 0; s < 8; ++s) {
            const int cur = s & 1;
            if (s < 7) {
                const int s1  = s + 1;
                const int ks1 = s1 >> 2, nt1 = s1 & 3;
                const uint32_t ba = b_base + nt1 * 16 * B_STRIDE + ks1 * 32;
                ldsm_x4(bh[cur ^ 1], ba);
                ldsm_x4(bl[cur ^ 1], ba + (B_LO - B_HI));
            }
            const int ks = s >> 2;
            const int j  = (s & 3) * 2;
            mma_bf16(acc[j],     ah[ks], bh[cur][0], bh[cur][1]);
            mma_bf16(acc[j],     al[ks], bh[cur][0], bh[cur][1]);
            mma_bf16(acc[j],     ah[ks], bl[cur][0], bl[cur][1]);
            mma_bf16(acc[j + 1], ah[ks], bh[cur][2], bh[cur][3]);
            mma_bf16(acc[j + 1], al[ks], bh[cur][2], bh[cur][3]);
            mma_bf16(acc[j + 1], ah[ks], bl[cur][2], bl[cur][3]);
        }

        if (c < NCHUNK - 1) {
            STS_A((c + 1) & 1);
            CP_WAIT0();
        }
        __syncthreads();
    }

    // ---- epilogue: relu(+bias), LN over 256 ch, psi, sigmoid ----
    // thread rows: pixgrp*16 + (lid>>2) and +8 ; cols nq*64 + j*8 + 2*(lid&3)+{0,1}
    {
        float s1a = 0.f, s2a = 0.f, sya = 0.f;
        float s1b = 0.f, s2b = 0.f, syb = 0.f;
        #pragma unroll
        for (int j = 0; j < 8; ++j) {
            const int c0 = nq * 64 + j * 8 + 2 * (lid & 3);
            const float bx0 = sBxg[c0], bx1 = sBxg[c0 + 1];
            const float u0 = sU[c0], u1 = sU[c0 + 1];
            float y;
            y = fmaxf(acc[j][0] + bx0, 0.f); s1a += y; s2a += y * y; sya += u0 * y;
            y = fmaxf(acc[j][1] + bx1, 0.f); s1a += y; s2a += y * y; sya += u1 * y;
            y = fmaxf(acc[j][2] + bx0, 0.f); s1b += y; s2b += y * y; syb += u0 * y;
            y = fmaxf(acc[j][3] + bx1, 0.f); s1b += y; s2b += y * y; syb += u1 * y;
        }
        #pragma unroll
        for (int m = 1; m <= 2; m <<= 1) {
            s1a += __shfl_xor_sync(0xffffffffu, s1a, m);
            s2a += __shfl_xor_sync(0xffffffffu, s2a, m);
            sya += __shfl_xor_sync(0xffffffffu, sya, m);
            s1b += __shfl_xor_sync(0xffffffffu, s1b, m);
            s2b += __shfl_xor_sync(0xffffffffu, s2b, m);
            syb += __shfl_xor_sync(0xffffffffu, syb, m);
        }
        if ((lid & 3) == 0) {
            const int p = pixgrp * 16 + (lid >> 2);
            sSums[p * 4 + nq]       = make_float4(s1a, s2a, sya, 0.f);
            sSums[(p + 8) * 4 + nq] = make_float4(s1b, s2b, syb, 0.f);
        }
    }
    __syncthreads();
    if (tid < PIXT) {
        float4 h0 = sSums[tid * 4], h1 = sSums[tid * 4 + 1];
        float4 h2 = sSums[tid * 4 + 2], h3 = sSums[tid * 4 + 3];
        float s1 = h0.x + h1.x + h2.x + h3.x;
        float s2 = h0.y + h1.y + h2.y + h3.y;
        float sy = h0.z + h1.z + h2.z + h3.z;
        float2 tot = sTot[0];
        float mean = s1 * (1.f / 256.f);
        float var  = s2 * (1.f / 256.f) - mean * mean;
        float rstd = rsqrtf(var + LN_EPS);
        float z = rstd * (sy - mean * tot.x) + tot.y + bpsi[0];
        sSig[tid] = 1.f / (1.f + expf(-z));
    }
    __syncthreads();

    // ---- gate: out[b,o,pix] = sig[pix] * x[b,o,pix] ----
    const size_t xbase = (size_t)b * CC * HWSZ + pix0;
    const int pq = tid & 15;
    float4 sg = *(const float4*)(sSig + pq * 4);
    #pragma unroll
    for (int it = 0; it < 8; ++it) {
        const int o = (tid >> 4) + it * 32;
        const size_t off = xbase + (size_t)o * HWSZ + pq * 4;
        float4 xv = *(const float4*)(x + off);
        float4 ov;
        ov.x = sg.x * xv.x; ov.y = sg.y * xv.y;
        ov.z = sg.z * xv.z; ov.w = sg.w * xv.w;
        *(float4*)(out + off) = ov;
    }
}

extern "C" void kernel_launch(void* const* d_in, const int* in_sizes, int n_in,
                              void* d_out, int out_size)
{
    const float* x        = (const float*)d_in[0];
    const float* g        = (const float*)d_in[1];
    const float* Wx       = (const float*)d_in[2];
    const float* Wg       = (const float*)d_in[3];
    const float* Wpsi     = (const float*)d_in[4];
    const float* ln_gamma = (const float*)d_in[5];
    const float* ln_beta  = (const float*)d_in[6];
    const float* bxg      = (const float*)d_in[7];
    const float* bpsi     = (const float*)d_in[8];
    float* out = (float*)d_out;

    cudaFuncSetAttribute(attn_gate_hmma,
                         cudaFuncAttributeMaxDynamicSharedMemorySize, SMEM_TOTAL);

    prep_w<<<512, 256>>>(Wx, Wg);
    attn_gate_hmma<<<1024, NTHR, SMEM_TOTAL>>>(x, g, ln_gamma, ln_beta, bxg,
                                               Wpsi, bpsi, out);
}

// round 11
// speedup vs baseline: 2.1100x; 1.1107x over previous
#include <cuda_runtime.h>
#include <cuda_bf16.h>
#include <cstdint>

#define CC     256
#define HWSZ   4096
#define KTOT   512       // x (256) then g (256)
#define PIXT   128       // pixels per CTA
#define KCH    32        // K per chunk
#define NCHUNK 16
#define NTHR   512
#define LN_EPS 1e-5f

// ---- W split scratch (L2-resident, 256KB each) ----
__device__ __nv_bfloat16 g_W_hi[CC * KTOT];   // [o][k], k = ch (x) then 256+ch (g)
__device__ __nv_bfloat16 g_W_lo[CC * KTOT];

__device__ __forceinline__ uint32_t smem_u32(const void* p) {
    uint32_t a;
    asm("{ .reg .u64 t; cvta.to.shared.u64 t, %1; cvt.u32.u64 %0, t; }"
        : "=r"(a) : "l"(p));
    return a;
}

__device__ __forceinline__ void ldsm_x4(uint32_t* r, uint32_t a) {
    asm volatile("ldmatrix.sync.aligned.m8n8.x4.shared.b16 {%0,%1,%2,%3}, [%4];"
                 : "=r"(r[0]), "=r"(r[1]), "=r"(r[2]), "=r"(r[3]) : "r"(a));
}
__device__ __forceinline__ void ldsm_x4_t(uint32_t* r, uint32_t a) {
    asm volatile("ldmatrix.sync.aligned.m8n8.x4.trans.shared.b16 {%0,%1,%2,%3}, [%4];"
                 : "=r"(r[0]), "=r"(r[1]), "=r"(r[2]), "=r"(r[3]) : "r"(a));
}
__device__ __forceinline__ void mma_bf16(float* c, const uint32_t* a,
                                         uint32_t b0, uint32_t b1) {
    asm volatile(
        "mma.sync.aligned.m16n8k16.row.col.f32.bf16.bf16.f32 "
        "{%0,%1,%2,%3}, {%4,%5,%6,%7}, {%8,%9}, {%0,%1,%2,%3};"
        : "+f"(c[0]), "+f"(c[1]), "+f"(c[2]), "+f"(c[3])
        : "r"(a[0]), "r"(a[1]), "r"(a[2]), "r"(a[3]), "r"(b0), "r"(b1));
}

#define CP_ASYNC16(sa, ga) \
    asm volatile("cp.async.cg.shared.global [%0], [%1], 16;" \
                 :: "r"(sa), "l"(ga) : "memory")
#define CP_COMMIT() asm volatile("cp.async.commit_group;" ::: "memory")
#define CP_WAIT0()  asm volatile("cp.async.wait_group 0;" ::: "memory")

__device__ __forceinline__ uint32_t pack_hi(float x0, float x1) {
    __nv_bfloat162 h = __floats2bfloat162_rn(x0, x1);
    return *reinterpret_cast<uint32_t*>(&h);
}
__device__ __forceinline__ uint32_t pack_lo(float x0, float x1) {
    float r0 = x0 - __bfloat162float(__float2bfloat16(x0));
    float r1 = x1 - __bfloat162float(__float2bfloat16(x1));
    __nv_bfloat162 h = __floats2bfloat162_rn(r0, r1);
    return *reinterpret_cast<uint32_t*>(&h);
}

// ---- prep: split W into bf16 hi/lo, layout [o][k0..511] ----
__global__ void prep_w(const float* __restrict__ Wx, const float* __restrict__ Wg)
{
    int idx = blockIdx.x * blockDim.x + threadIdx.x;   // 0..131071
    int o = idx >> 9, k = idx & 511;
    float v = (k < 256) ? Wx[o * 256 + k] : Wg[o * 256 + (k - 256)];
    __nv_bfloat16 hi = __float2bfloat16(v);
    g_W_hi[idx] = hi;
    g_W_lo[idx] = __float2bfloat16(v - __bfloat162float(hi));
}

// ---------------- smem layout (dynamic) ----------------
#define OFF_U     0
#define OFF_BXG   1024
#define OFF_SIG   2048      // 128 * 4B = 512
#define OFF_SUMS  2560      // 128 px * 4 quarters * float4 = 8192
#define OFF_RED   10752     // 16 * float2
#define OFF_TOT   10880
#define OFF_TILE  11264
#define A_STRIDE  272       // 128 px * 2B + 16 pad
#define B_STRIDE  80        // 32 k * 2B + 16 pad
#define A_HI      0
#define A_LO      8704
#define B_HI      17408
#define B_LO      37888
#define BUF_SZ    58368
#define SMEM_TOTAL (OFF_TILE + 2 * BUF_SZ)   // 128000

__global__ void __launch_bounds__(NTHR, 1)
attn_gate_hmma(const float* __restrict__ x,
               const float* __restrict__ g,
               const float* __restrict__ ln_gamma,
               const float* __restrict__ ln_beta,
               const float* __restrict__ bxg,
               const float* __restrict__ Wpsi,
               const float* __restrict__ bpsi,
               float* __restrict__ out)
{
    extern __shared__ char smem[];
    const uint32_t sb = smem_u32(smem);
    const int tid = threadIdx.x;
    const int wid = tid >> 5, lid = tid & 31;
    const int pixgrp = wid >> 2;          // 0..3 (32 pixels each)
    const int nq     = wid & 3;           // 0..3 (64 channels each)
    const int b    = blockIdx.x >> 5;     // 32 pixel tiles per batch
    const int pix0 = (blockIdx.x & 31) * PIXT;

    float* sU   = (float*)(smem + OFF_U);
    float* sBxg = (float*)(smem + OFF_BXG);
    float* sSig = (float*)(smem + OFF_SIG);
    float4* sSums = (float4*)(smem + OFF_SUMS);
    float2* sRed  = (float2*)(smem + OFF_RED);
    float2* sTot  = (float2*)(smem + OFF_TOT);

    // ---- B tile async copy: 512 threads = 256 hi rows + 256 lo rows ----
    const int brow = tid & 255;
    const int bhl  = tid >> 8;            // 0 = hi, 1 = lo
    const __nv_bfloat16* bsrc_base = bhl ? g_W_lo : g_W_hi;
    const uint32_t bdst_off = (bhl ? B_LO : B_HI) + brow * B_STRIDE;

    #define CPA_B(c, buf) do {                                                 \
        uint32_t dst = sb + OFF_TILE + (buf) * BUF_SZ + bdst_off;              \
        const char* w = (const char*)(bsrc_base + (size_t)brow * KTOT + (c) * KCH); \
        CP_ASYNC16(dst,      w);      CP_ASYNC16(dst + 16, w + 16);            \
        CP_ASYNC16(dst + 32, w + 32); CP_ASYNC16(dst + 48, w + 48);            \
    } while (0)

    // ---- A tile: 32 k-rows x 128 px, two float4 per thread ----
    float4 pa0, pa1;
    const int arow = tid >> 4;            // 0..31
    const int apq  = tid & 15;            // pixel quad (first 64 px; +16 for rest)

    #define LDG_A(c) do {                                                      \
        const float* asrc = (((c) < 8) ? x : g) +                              \
            ((size_t)b * CC + ((c) & 7) * KCH) * HWSZ + pix0;                  \
        pa0 = *(const float4*)(asrc + (size_t)arow * HWSZ + apq * 4);          \
        pa1 = *(const float4*)(asrc + (size_t)arow * HWSZ + 64 + apq * 4);     \
    } while (0)

    #define STS_A(buf) do {                                                    \
        char* base = smem + OFF_TILE + (buf) * BUF_SZ + arow * A_STRIDE;       \
        uint32_t h0 = pack_hi(pa0.x, pa0.y), h1 = pack_hi(pa0.z, pa0.w);       \
        uint32_t l0 = pack_lo(pa0.x, pa0.y), l1 = pack_lo(pa0.z, pa0.w);       \
        *(uint2*)(base + A_HI + apq * 8) = make_uint2(h0, h1);                 \
        *(uint2*)(base + A_LO + apq * 8) = make_uint2(l0, l1);                 \
        h0 = pack_hi(pa1.x, pa1.y); h1 = pack_hi(pa1.z, pa1.w);                \
        l0 = pack_lo(pa1.x, pa1.y); l1 = pack_lo(pa1.z, pa1.w);                \
        *(uint2*)(base + A_HI + 128 + apq * 8) = make_uint2(h0, h1);           \
        *(uint2*)(base + A_LO + 128 + apq * 8) = make_uint2(l0, l1);           \
    } while (0)

    if (tid < 256) {   // epilogue params + totals (su = Σwpsi*gamma, ws = Σwpsi*beta)
        float wp = Wpsi[tid];
        float u  = wp * ln_gamma[tid];
        float wb = wp * ln_beta[tid];
        sU[tid]   = u;
        sBxg[tid] = bxg[tid];
        float us = u, ws = wb;
        #pragma unroll
        for (int m = 16; m >= 1; m >>= 1) {
            us += __shfl_xor_sync(0xffffffffu, us, m);
            ws += __shfl_xor_sync(0xffffffffu, ws, m);
        }
        if (lid == 0) sRed[wid] = make_float2(us, ws);
    }
    __syncthreads();
    if (tid == 0) {
        float us = 0.f, ws = 0.f;
        #pragma unroll
        for (int w = 0; w < 8; ++w) { us += sRed[w].x; ws += sRed[w].y; }
        sTot[0] = make_float2(us, ws);
    }

    float acc[2][8][4];                    // [mrow][n-col pair][quad]
    #pragma unroll
    for (int mr = 0; mr < 2; ++mr)
        #pragma unroll
        for (int j = 0; j < 8; ++j)
            #pragma unroll
            for (int q = 0; q < 4; ++q) acc[mr][j][q] = 0.f;

    // prologue: chunk 0 into buffer 0
    CPA_B(0, 0);
    CP_COMMIT();
    LDG_A(0);
    STS_A(0);
    CP_WAIT0();
    __syncthreads();

    const int m0 = pixgrp * 32;
    const int al_k = (lid & 7) + ((lid >> 4) << 3);
    const int al_m = m0 + (((lid >> 3) & 1) << 3);
    const int bl_n = ((lid >> 4) << 3) + (lid & 7);
    const int bl_k = ((lid >> 3) & 1) << 3;

    for (int c = 0; c < NCHUNK; ++c) {
        if (c < NCHUNK - 1) {
            CPA_B(c + 1, (c + 1) & 1);
            CP_COMMIT();
            LDG_A(c + 1);
        }

        const uint32_t tb = sb + OFF_TILE + (c & 1) * BUF_SZ;
        const uint32_t b_base = tb + B_HI + (nq * 64 + bl_n) * B_STRIDE + bl_k * 2;

        #pragma unroll
        for (int ks = 0; ks < 2; ++ks) {
            // A fragments for both m-rows of this k-step
            const uint32_t a_addr = tb + A_HI + (ks * 16 + al_k) * A_STRIDE + al_m * 2;
            uint32_t ah0[4], al0[4], ah1[4], al1[4];
            ldsm_x4_t(ah0, a_addr);
            ldsm_x4_t(al0, a_addr + (A_LO - A_HI));
            ldsm_x4_t(ah1, a_addr + 32);            // m + 16 px = +32 bytes
            ldsm_x4_t(al1, a_addr + 32 + (A_LO - A_HI));

            #pragma unroll
            for (int ntt = 0; ntt < 4; ++ntt) {
                const uint32_t ba = b_base + ntt * 16 * B_STRIDE + ks * 32;
                uint32_t bh[4], bl[4];
                ldsm_x4(bh, ba);
                ldsm_x4(bl, ba + (B_LO - B_HI));
                const int j = ntt * 2;
                mma_bf16(acc[0][j],     ah0, bh[0], bh[1]);
                mma_bf16(acc[1][j],     ah1, bh[0], bh[1]);
                mma_bf16(acc[0][j + 1], ah0, bh[2], bh[3]);
                mma_bf16(acc[1][j + 1], ah1, bh[2], bh[3]);
                mma_bf16(acc[0][j],     al0, bh[0], bh[1]);
                mma_bf16(acc[1][j],     al1, bh[0], bh[1]);
                mma_bf16(acc[0][j + 1], al0, bh[2], bh[3]);
                mma_bf16(acc[1][j + 1], al1, bh[2], bh[3]);
                mma_bf16(acc[0][j],     ah0, bl[0], bl[1]);
                mma_bf16(acc[1][j],     ah1, bl[0], bl[1]);
                mma_bf16(acc[0][j + 1], ah0, bl[2], bl[3]);
                mma_bf16(acc[1][j + 1], ah1, bl[2], bl[3]);
            }
        }

        if (c < NCHUNK - 1) {
            STS_A((c + 1) & 1);
            CP_WAIT0();
        }
        __syncthreads();
    }

    // ---- epilogue: relu(+bias), LN over 256 ch, psi, sigmoid ----
    // rows: pixgrp*32 + mr*16 + (lid>>2) and +8 ; cols nq*64 + j*8 + 2*(lid&3)+{0,1}
    {
        float s1[2][2], s2[2][2], sy[2][2];
        #pragma unroll
        for (int mr = 0; mr < 2; ++mr)
            #pragma unroll
            for (int h = 0; h < 2; ++h) { s1[mr][h] = 0.f; s2[mr][h] = 0.f; sy[mr][h] = 0.f; }

        #pragma unroll
        for (int mr = 0; mr < 2; ++mr) {
            #pragma unroll
            for (int j = 0; j < 8; ++j) {
                const int c0 = nq * 64 + j * 8 + 2 * (lid & 3);
                const float bx0 = sBxg[c0], bx1 = sBxg[c0 + 1];
                const float u0 = sU[c0], u1 = sU[c0 + 1];
                float y;
                y = fmaxf(acc[mr][j][0] + bx0, 0.f); s1[mr][0] += y; s2[mr][0] += y * y; sy[mr][0] += u0 * y;
                y = fmaxf(acc[mr][j][1] + bx1, 0.f); s1[mr][0] += y; s2[mr][0] += y * y; sy[mr][0] += u1 * y;
                y = fmaxf(acc[mr][j][2] + bx0, 0.f); s1[mr][1] += y; s2[mr][1] += y * y; sy[mr][1] += u0 * y;
                y = fmaxf(acc[mr][j][3] + bx1, 0.f); s1[mr][1] += y; s2[mr][1] += y * y; sy[mr][1] += u1 * y;
            }
        }
        #pragma unroll
        for (int m = 1; m <= 2; m <<= 1) {
            #pragma unroll
            for (int mr = 0; mr < 2; ++mr)
                #pragma unroll
                for (int h = 0; h < 2; ++h) {
                    s1[mr][h] += __shfl_xor_sync(0xffffffffu, s1[mr][h], m);
                    s2[mr][h] += __shfl_xor_sync(0xffffffffu, s2[mr][h], m);
                    sy[mr][h] += __shfl_xor_sync(0xffffffffu, sy[mr][h], m);
                }
        }
        if ((lid & 3) == 0) {
            #pragma unroll
            for (int mr = 0; mr < 2; ++mr) {
                const int p = pixgrp * 32 + mr * 16 + (lid >> 2);
                sSums[p * 4 + nq]       = make_float4(s1[mr][0], s2[mr][0], sy[mr][0], 0.f);
                sSums[(p + 8) * 4 + nq] = make_float4(s1[mr][1], s2[mr][1], sy[mr][1], 0.f);
            }
        }
    }
    __syncthreads();
    if (tid < PIXT) {
        float4 h0 = sSums[tid * 4], h1 = sSums[tid * 4 + 1];
        float4 h2 = sSums[tid * 4 + 2], h3 = sSums[tid * 4 + 3];
        float s1 = h0.x + h1.x + h2.x + h3.x;
        float s2 = h0.y + h1.y + h2.y + h3.y;
        float sy = h0.z + h1.z + h2.z + h3.z;
        float2 tot = sTot[0];
        float mean = s1 * (1.f / 256.f);
        float var  = s2 * (1.f / 256.f) - mean * mean;
        float rstd = rsqrtf(var + LN_EPS);
        float z = rstd * (sy - mean * tot.x) + tot.y + bpsi[0];
        sSig[tid] = 1.f / (1.f + expf(-z));
    }
    __syncthreads();

    // ---- gate: out[b,o,pix] = sig[pix] * x[b,o,pix] ----
    const size_t xbase = (size_t)b * CC * HWSZ + pix0;
    const int pq = tid & 31;              // 32 pixel-quads = 128 px
    float4 sg = *(const float4*)(sSig + pq * 4);
    #pragma unroll
    for (int it = 0; it < 16; ++it) {
        const int o = (tid >> 5) + it * 16;
        const size_t off = xbase + (size_t)o * HWSZ + pq * 4;
        float4 xv = *(const float4*)(x + off);
        float4 ov;
        ov.x = sg.x * xv.x; ov.y = sg.y * xv.y;
        ov.z = sg.z * xv.z; ov.w = sg.w * xv.w;
        *(float4*)(out + off) = ov;
    }
}

extern "C" void kernel_launch(void* const* d_in, const int* in_sizes, int n_in,
                              void* d_out, int out_size)
{
    const float* x        = (const float*)d_in[0];
    const float* g        = (const float*)d_in[1];
    const float* Wx       = (const float*)d_in[2];
    const float* Wg       = (const float*)d_in[3];
    const float* Wpsi     = (const float*)d_in[4];
    const float* ln_gamma = (const float*)d_in[5];
    const float* ln_beta  = (const float*)d_in[6];
    const float* bxg      = (const float*)d_in[7];
    const float* bpsi     = (const float*)d_in[8];
    float* out = (float*)d_out;

    cudaFuncSetAttribute(attn_gate_hmma,
                         cudaFuncAttributeMaxDynamicSharedMemorySize, SMEM_TOTAL);

    prep_w<<<512, 256>>>(Wx, Wg);
    attn_gate_hmma<<<512, NTHR, SMEM_TOTAL>>>(x, g, ln_gamma, ln_beta, bxg,
                                              Wpsi, bpsi, out);
}

// round 12
// speedup vs baseline: 4.1846x; 1.9832x over previous
#include <cuda_runtime.h>
#include <cuda_fp16.h>
#include <cstdint>

#define CC     256
#define HWSZ   4096
#define KTOT   512       // x (256) then g (256)
#define PIXT   128       // pixels per CTA
#define KCH    64        // K per smem chunk
#define NCHUNK 8
#define NTHR   512
#define LN_EPS 1e-5f

// ---- W fp16 scratch (L2-resident, 256KB) ----
__device__ __half g_W_h[CC * KTOT];           // [o][k], k = ch (x) then 256+ch (g)

__device__ __forceinline__ uint32_t smem_u32(const void* p) {
    uint32_t a;
    asm("{ .reg .u64 t; cvta.to.shared.u64 t, %1; cvt.u32.u64 %0, t; }"
        : "=r"(a) : "l"(p));
    return a;
}

__device__ __forceinline__ void ldsm_x4(uint32_t* r, uint32_t a) {
    asm volatile("ldmatrix.sync.aligned.m8n8.x4.shared.b16 {%0,%1,%2,%3}, [%4];"
                 : "=r"(r[0]), "=r"(r[1]), "=r"(r[2]), "=r"(r[3]) : "r"(a));
}
__device__ __forceinline__ void ldsm_x4_t(uint32_t* r, uint32_t a) {
    asm volatile("ldmatrix.sync.aligned.m8n8.x4.trans.shared.b16 {%0,%1,%2,%3}, [%4];"
                 : "=r"(r[0]), "=r"(r[1]), "=r"(r[2]), "=r"(r[3]) : "r"(a));
}
__device__ __forceinline__ void mma_f16(float* c, const uint32_t* a,
                                        uint32_t b0, uint32_t b1) {
    asm volatile(
        "mma.sync.aligned.m16n8k16.row.col.f32.f16.f16.f32 "
        "{%0,%1,%2,%3}, {%4,%5,%6,%7}, {%8,%9}, {%0,%1,%2,%3};"
        : "+f"(c[0]), "+f"(c[1]), "+f"(c[2]), "+f"(c[3])
        : "r"(a[0]), "r"(a[1]), "r"(a[2]), "r"(a[3]), "r"(b0), "r"(b1));
}

#define CP_ASYNC16(sa, ga) \
    asm volatile("cp.async.cg.shared.global [%0], [%1], 16;" \
                 :: "r"(sa), "l"(ga) : "memory")
#define CP_COMMIT() asm volatile("cp.async.commit_group;" ::: "memory")
#define CP_WAIT0()  asm volatile("cp.async.wait_group 0;" ::: "memory")

__device__ __forceinline__ uint32_t pack_h2(float x0, float x1) {
    __half2 h = __floats2half2_rn(x0, x1);
    return *reinterpret_cast<uint32_t*>(&h);
}

// ---- prep: W -> fp16, layout [o][k0..511] ----
__global__ void prep_w(const float* __restrict__ Wx, const float* __restrict__ Wg)
{
    int idx = blockIdx.x * blockDim.x + threadIdx.x;   // 0..131071
    int o = idx >> 9, k = idx & 511;
    float v = (k < 256) ? Wx[o * 256 + k] : Wg[o * 256 + (k - 256)];
    g_W_h[idx] = __float2half(v);
}

// ---------------- smem layout (dynamic) ----------------
#define OFF_U     0
#define OFF_BXG   1024
#define OFF_SIG   2048      // 128 * 4B
#define OFF_SUMS  2560      // 128 px * 4 quarters * float4 = 8192
#define OFF_RED   10752     // 16 * float2
#define OFF_TOT   10880
#define OFF_TILE  11264
#define A_STRIDE  272       // 128 px * 2B + 16 pad (ldsm conflict-free)
#define B_STRIDE  144       // 64 k * 2B + 16 pad
#define A_OFF     0
#define B_OFF     17408     // 64 rows * 272
#define BUF_SZ    54272     // + 256 rows * 144
#define SMEM_TOTAL (OFF_TILE + 2 * BUF_SZ)   // 119808

__global__ void __launch_bounds__(NTHR, 1)
attn_gate_hmma(const float* __restrict__ x,
               const float* __restrict__ g,
               const float* __restrict__ ln_gamma,
               const float* __restrict__ ln_beta,
               const float* __restrict__ bxg,
               const float* __restrict__ Wpsi,
               const float* __restrict__ bpsi,
               float* __restrict__ out)
{
    extern __shared__ char smem[];
    const uint32_t sb = smem_u32(smem);
    const int tid = threadIdx.x;
    const int wid = tid >> 5, lid = tid & 31;
    const int pixgrp = wid >> 2;          // 0..3 (32 pixels each)
    const int nq     = wid & 3;           // 0..3 (64 channels each)
    const int b    = blockIdx.x >> 5;     // 32 pixel tiles per batch
    const int pix0 = (blockIdx.x & 31) * PIXT;

    float* sU   = (float*)(smem + OFF_U);
    float* sBxg = (float*)(smem + OFF_BXG);
    float* sSig = (float*)(smem + OFF_SIG);
    float4* sSums = (float4*)(smem + OFF_SUMS);
    float2* sRed  = (float2*)(smem + OFF_RED);
    float2* sTot  = (float2*)(smem + OFF_TOT);

    // ---- B tile: 256 rows x 128B; 512 threads = half-row (64B) each ----
    const int brow = tid >> 1;
    const int bseg = tid & 1;
    const uint32_t bdst_off = B_OFF + brow * B_STRIDE + bseg * 64;

    #define CPA_B(c, buf) do {                                                 \
        uint32_t dst = sb + OFF_TILE + (buf) * BUF_SZ + bdst_off;              \
        const char* w = (const char*)(g_W_h + (size_t)brow * KTOT + (c) * KCH) \
                        + bseg * 64;                                           \
        CP_ASYNC16(dst,      w);      CP_ASYNC16(dst + 16, w + 16);            \
        CP_ASYNC16(dst + 32, w + 32); CP_ASYNC16(dst + 48, w + 48);            \
    } while (0)

    // ---- A tile: 64 k-rows x 128 px; thread = 16 px of one row ----
    float4 pa[4];
    const int arow = tid >> 3;            // 0..63
    const int aseg = tid & 7;             // 16-px segment

    #define LDG_A(c) do {                                                      \
        const float* asrc = (((c) < 4) ? x : g) +                              \
            ((size_t)b * CC + ((c) & 3) * KCH) * HWSZ + pix0 +                 \
            (size_t)arow * HWSZ + aseg * 16;                                   \
        pa[0] = *(const float4*)(asrc);                                        \
        pa[1] = *(const float4*)(asrc + 4);                                    \
        pa[2] = *(const float4*)(asrc + 8);                                    \
        pa[3] = *(const float4*)(asrc + 12);                                   \
    } while (0)

    #define STS_A(buf) do {                                                    \
        char* base = smem + OFF_TILE + (buf) * BUF_SZ + A_OFF +                \
                     arow * A_STRIDE + aseg * 32;                              \
        *(uint2*)(base)      = make_uint2(pack_h2(pa[0].x, pa[0].y),           \
                                          pack_h2(pa[0].z, pa[0].w));          \
        *(uint2*)(base + 8)  = make_uint2(pack_h2(pa[1].x, pa[1].y),           \
                                          pack_h2(pa[1].z, pa[1].w));          \
        *(uint2*)(base + 16) = make_uint2(pack_h2(pa[2].x, pa[2].y),           \
                                          pack_h2(pa[2].z, pa[2].w));          \
        *(uint2*)(base + 24) = make_uint2(pack_h2(pa[3].x, pa[3].y),           \
                                          pack_h2(pa[3].z, pa[3].w));          \
    } while (0)

    if (tid < 256) {   // epilogue params + totals (su = Σwpsi*gamma, ws = Σwpsi*beta)
        float wp = Wpsi[tid];
        float u  = wp * ln_gamma[tid];
        float wb = wp * ln_beta[tid];
        sU[tid]   = u;
        sBxg[tid] = bxg[tid];
        float us = u, ws = wb;
        #pragma unroll
        for (int m = 16; m >= 1; m >>= 1) {
            us += __shfl_xor_sync(0xffffffffu, us, m);
            ws += __shfl_xor_sync(0xffffffffu, ws, m);
        }
        if (lid == 0) sRed[wid] = make_float2(us, ws);
    }
    __syncthreads();
    if (tid == 0) {
        float us = 0.f, ws = 0.f;
        #pragma unroll
        for (int w = 0; w < 8; ++w) { us += sRed[w].x; ws += sRed[w].y; }
        sTot[0] = make_float2(us, ws);
    }

    float acc[2][8][4];                    // [mrow][n-col pair][quad]
    #pragma unroll
    for (int mr = 0; mr < 2; ++mr)
        #pragma unroll
        for (int j = 0; j < 8; ++j)
            #pragma unroll
            for (int q = 0; q < 4; ++q) acc[mr][j][q] = 0.f;

    // prologue: chunk 0 into buffer 0
    CPA_B(0, 0);
    CP_COMMIT();
    LDG_A(0);
    STS_A(0);
    CP_WAIT0();
    __syncthreads();

    const int m0 = pixgrp * 32;
    const int al_k = (lid & 7) + ((lid >> 4) << 3);
    const int al_m = m0 + (((lid >> 3) & 1) << 3);
    const int bl_n = ((lid >> 4) << 3) + (lid & 7);
    const int bl_k = ((lid >> 3) & 1) << 3;

    for (int c = 0; c < NCHUNK; ++c) {
        if (c < NCHUNK - 1) {
            CPA_B(c + 1, (c + 1) & 1);
            CP_COMMIT();
            LDG_A(c + 1);
        }

        const uint32_t tb = sb + OFF_TILE + (c & 1) * BUF_SZ;
        const uint32_t b_base = tb + B_OFF + (nq * 64 + bl_n) * B_STRIDE + bl_k * 2;

        #pragma unroll
        for (int ks = 0; ks < 4; ++ks) {
            const uint32_t a_addr = tb + A_OFF + (ks * 16 + al_k) * A_STRIDE + al_m * 2;
            uint32_t a0[4], a1[4];
            ldsm_x4_t(a0, a_addr);
            ldsm_x4_t(a1, a_addr + 32);            // m + 16 px
            #pragma unroll
            for (int ntt = 0; ntt < 4; ++ntt) {
                const uint32_t ba = b_base + ntt * 16 * B_STRIDE + ks * 32;
                uint32_t bh[4];
                ldsm_x4(bh, ba);
                const int j = ntt * 2;
                mma_f16(acc[0][j],     a0, bh[0], bh[1]);
                mma_f16(acc[1][j],     a1, bh[0], bh[1]);
                mma_f16(acc[0][j + 1], a0, bh[2], bh[3]);
                mma_f16(acc[1][j + 1], a1, bh[2], bh[3]);
            }
        }

        if (c < NCHUNK - 1) {
            STS_A((c + 1) & 1);
            CP_WAIT0();
        }
        __syncthreads();
    }

    // ---- epilogue: relu(+bias), LN over 256 ch, psi, sigmoid ----
    // rows: pixgrp*32 + mr*16 + (lid>>2) and +8 ; cols nq*64 + j*8 + 2*(lid&3)+{0,1}
    {
        float s1[2][2], s2[2][2], sy[2][2];
        #pragma unroll
        for (int mr = 0; mr < 2; ++mr)
            #pragma unroll
            for (int h = 0; h < 2; ++h) { s1[mr][h] = 0.f; s2[mr][h] = 0.f; sy[mr][h] = 0.f; }

        #pragma unroll
        for (int mr = 0; mr < 2; ++mr) {
            #pragma unroll
            for (int j = 0; j < 8; ++j) {
                const int c0 = nq * 64 + j * 8 + 2 * (lid & 3);
                const float bx0 = sBxg[c0], bx1 = sBxg[c0 + 1];
                const float u0 = sU[c0], u1 = sU[c0 + 1];
                float y;
                y = fmaxf(acc[mr][j][0] + bx0, 0.f); s1[mr][0] += y; s2[mr][0] += y * y; sy[mr][0] += u0 * y;
                y = fmaxf(acc[mr][j][1] + bx1, 0.f); s1[mr][0] += y; s2[mr][0] += y * y; sy[mr][0] += u1 * y;
                y = fmaxf(acc[mr][j][2] + bx0, 0.f); s1[mr][1] += y; s2[mr][1] += y * y; sy[mr][1] += u0 * y;
                y = fmaxf(acc[mr][j][3] + bx1, 0.f); s1[mr][1] += y; s2[mr][1] += y * y; sy[mr][1] += u1 * y;
            }
        }
        #pragma unroll
        for (int m = 1; m <= 2; m <<= 1) {
            #pragma unroll
            for (int mr = 0; mr < 2; ++mr)
                #pragma unroll
                for (int h = 0; h < 2; ++h) {
                    s1[mr][h] += __shfl_xor_sync(0xffffffffu, s1[mr][h], m);
                    s2[mr][h] += __shfl_xor_sync(0xffffffffu, s2[mr][h], m);
                    sy[mr][h] += __shfl_xor_sync(0xffffffffu, sy[mr][h], m);
                }
        }
        if ((lid & 3) == 0) {
            #pragma unroll
            for (int mr = 0; mr < 2; ++mr) {
                const int p = pixgrp * 32 + mr * 16 + (lid >> 2);
                sSums[p * 4 + nq]       = make_float4(s1[mr][0], s2[mr][0], sy[mr][0], 0.f);
                sSums[(p + 8) * 4 + nq] = make_float4(s1[mr][1], s2[mr][1], sy[mr][1], 0.f);
            }
        }
    }
    __syncthreads();
    if (tid < PIXT) {
        float4 h0 = sSums[tid * 4], h1 = sSums[tid * 4 + 1];
        float4 h2 = sSums[tid * 4 + 2], h3 = sSums[tid * 4 + 3];
        float s1 = h0.x + h1.x + h2.x + h3.x;
        float s2 = h0.y + h1.y + h2.y + h3.y;
        float sy = h0.z + h1.z + h2.z + h3.z;
        float2 tot = sTot[0];
        float mean = s1 * (1.f / 256.f);
        float var  = s2 * (1.f / 256.f) - mean * mean;
        float rstd = rsqrtf(var + LN_EPS);
        float z = rstd * (sy - mean * tot.x) + tot.y + bpsi[0];
        sSig[tid] = 1.f / (1.f + expf(-z));
    }
    __syncthreads();

    // ---- gate: out[b,o,pix] = sig[pix] * x[b,o,pix] ----
    const size_t xbase = (size_t)b * CC * HWSZ + pix0;
    const int pq = tid & 31;              // 32 pixel-quads = 128 px
    float4 sg = *(const float4*)(sSig + pq * 4);
    #pragma unroll
    for (int it = 0; it < 16; ++it) {
        const int o = (tid >> 5) + it * 16;
        const size_t off = xbase + (size_t)o * HWSZ + pq * 4;
        float4 xv = *(const float4*)(x + off);
        float4 ov;
        ov.x = sg.x * xv.x; ov.y = sg.y * xv.y;
        ov.z = sg.z * xv.z; ov.w = sg.w * xv.w;
        *(float4*)(out + off) = ov;
    }
}

extern "C" void kernel_launch(void* const* d_in, const int* in_sizes, int n_in,
                              void* d_out, int out_size)
{
    const float* x        = (const float*)d_in[0];
    const float* g        = (const float*)d_in[1];
    const float* Wx       = (const float*)d_in[2];
    const float* Wg       = (const float*)d_in[3];
    const float* Wpsi     = (const float*)d_in[4];
    const float* ln_gamma = (const float*)d_in[5];
    const float* ln_beta  = (const float*)d_in[6];
    const float* bxg      = (const float*)d_in[7];
    const float* bpsi     = (const float*)d_in[8];
    float* out = (float*)d_out;

    cudaFuncSetAttribute(attn_gate_hmma,
                         cudaFuncAttributeMaxDynamicSharedMemorySize, SMEM_TOTAL);

    prep_w<<<512, 256>>>(Wx, Wg);
    attn_gate_hmma<<<512, NTHR, SMEM_TOTAL>>>(x, g, ln_gamma, ln_beta, bxg,
                                              Wpsi, bpsi, out);
}